// round 17
// baseline (speedup 1.0000x reference)
#include <cuda_runtime.h>
#include <cuda_bf16.h>

// Problem constants (from reference)
#define BATCH 1024
#define DDIM  512
#define FDIM  4096

// out[b*D+d] = bias[d] + mask[b*D+d], vectorized float4, one-shot grid.
__global__ __launch_bounds__(256)
void tied_init_kernel(float4* __restrict__ out4,
                      const float4* __restrict__ bias4,
                      const float4* __restrict__ mask4,
                      int total4) {
    int i = blockIdx.x * blockDim.x + threadIdx.x;
    if (i >= total4) return;
    float4 m = mask4[i];
    float4 bv = __ldg(&bias4[i & (DDIM / 4 - 1)]);   // D/4 = 128, power of 2
    m.x += bv.x; m.y += bv.y; m.z += bv.z; m.w += bv.w;
    out4[i] = m;
}

// Best-measured scatter body (65.0us @ 256thr): one 4-nnz packet per thread,
// 4 front-batched LDG.128s, L1-resident weight gathers, fire-and-forget
// atomicAdd (REDG). This round probes the last untested tuning axis:
// 128-thread blocks (~19.5k one-shot blocks) for finer wave packing /
// spread absorption. SASS body identical; only launch geometry changes.
__global__ __launch_bounds__(128)
void tied_scatter_kernel(const float4* __restrict__ vals4,
                         const int4* __restrict__ b4,
                         const int4* __restrict__ d4,
                         const int4* __restrict__ f4,
                         const float* __restrict__ w,
                         float* __restrict__ out,
                         int n4) {
    const int i = blockIdx.x * blockDim.x + threadIdx.x;
    if (i >= n4) return;

    // ---- front-batched loads (4x LDG.128) ----
    float4 v  = vals4[i];
    int4  bi = b4[i];
    int4  di = d4[i];
    int4  fi = f4[i];

    // weight gathers: 16KB table, L1-resident
    float w0 = __ldg(&w[fi.x]);
    float w1 = __ldg(&w[fi.y]);
    float w2 = __ldg(&w[fi.z]);
    float w3 = __ldg(&w[fi.w]);

    atomicAdd(&out[bi.x * DDIM + di.x], v.x * w0);
    atomicAdd(&out[bi.y * DDIM + di.y], v.y * w1);
    atomicAdd(&out[bi.z * DDIM + di.z], v.z * w2);
    atomicAdd(&out[bi.w * DDIM + di.w], v.w * w3);
}

// Tail handler for NNZ not divisible by 4 (defensive; NNZ=10M is divisible,
// so this never launches in practice).
__global__ __launch_bounds__(256)
void tied_scatter_tail_kernel(const float* __restrict__ vals,
                              const int* __restrict__ b,
                              const int* __restrict__ d,
                              const int* __restrict__ f,
                              const float* __restrict__ w,
                              float* __restrict__ out,
                              int start, int n) {
    int i = start + blockIdx.x * blockDim.x + threadIdx.x;
    if (i >= n) return;
    atomicAdd(&out[b[i] * DDIM + d[i]], vals[i] * __ldg(&w[f[i]]));
}

extern "C" void kernel_launch(void* const* d_in, const int* in_sizes, int n_in,
                              void* d_out, int out_size) {
    // metadata order: values, b_idx, d_idx, f_idx, weight, bias, mask
    const float* values = (const float*)d_in[0];
    const int*   b_idx  = (const int*)d_in[1];
    const int*   d_idx  = (const int*)d_in[2];
    const int*   f_idx  = (const int*)d_in[3];
    const float* weight = (const float*)d_in[4];
    const float* bias   = (const float*)d_in[5];
    const float* mask   = (const float*)d_in[6];
    float* out = (float*)d_out;

    const int nnz = in_sizes[0];

    // 1) init: out = bias + mask  (out_size = B*D = 524288, /4 = 131072)
    {
        int total4 = out_size / 4;
        int blocks = (total4 + 255) / 256;               // 512 blocks, one-shot
        tied_init_kernel<<<blocks, 256>>>((float4*)out,
                                          (const float4*)bias,
                                          (const float4*)mask,
                                          total4);
    }

    // 2) scatter: one 4-nnz packet per thread, 128-thread blocks (~19532)
    {
        int n4 = nnz / 4;
        int blocks = (n4 + 127) / 128;
        tied_scatter_kernel<<<blocks, 128>>>((const float4*)values,
                                             (const int4*)b_idx,
                                             (const int4*)d_idx,
                                             (const int4*)f_idx,
                                             weight, out, n4);
        int tail_start = n4 * 4;
        int tail = nnz - tail_start;
        if (tail > 0) {
            tied_scatter_tail_kernel<<<1, 256>>>(values, b_idx, d_idx, f_idx,
                                                 weight, out, tail_start, nnz);
        }
    }
}